// round 17
// baseline (speedup 1.0000x reference)
#include <cuda_runtime.h>
#include <cuda_fp16.h>
#include <math.h>

// Problem constants
#define MM       2048           // patches
#define NC       4              // compartments
#define NSTEPS   128
#define BETA_F   0.25f
#define TRAJ_ELEMS (NSTEPS * MM * (NC + 1))   // 1310720

// 128 persistent blocks, 16 rows of R each, 256 threads (8 warps).
// Warp w: rows 4*(w>>1)..+3 over column half (w&1)  [split-K].
#define NBLK     128
#define ROWS     16
#define NTHREADS 256

// SMEM: R fp16 tile (64KB) + part[32] + dsum[16 dbl]. x/p live in REGISTERS.
#define SMEM_BYTES (ROWS * MM * 2 + 32 * 4 + 16 * 8)

// -------- persistent device state (monotonic; re-derived every launch) ------
__device__ float        g_x[MM];            // rho[:,0] (phase-A input vector)
__device__ float        g_p[MM];            // infect_prob (phase-B input vector)
__device__ float        g_part[NBLK * MM];  // per-block column partials (ntot)
__device__ double       g_bsum[NBLK];       // per-block |traj| sums (agreement)
__device__ unsigned int g_bar_in = 0;       // monotonic arrival counter (ONLY word)

// R15/R16 champion barrier, byte-identical (clean attribution for the
// compute-side change this round): single word, arrival == release,
// sleepless GPU-scope relaxed poll, fence-fence ordering, monotonic.
__device__ __forceinline__ void gridsync(unsigned int &gen) {
    __syncthreads();
    if (threadIdx.x == 0) {
        const unsigned int tgt = (gen + 1u) * (unsigned)NBLK;
        __threadfence();                                   // publish writes (release)
        unsigned int a = atomicAdd(&g_bar_in, 1u);
        if (a != tgt - 1u) {                               // not the last arriver
            unsigned int f;
            do {   // dependent relaxed load: one L2 round trip per iteration
                asm volatile("ld.relaxed.gpu.u32 %0, [%1];"
                             : "=r"(f) : "l"(&g_bar_in) : "memory");
            } while ((int)(f - tgt) < 0);
        }
        __threadfence();                                   // acquire side
        gen++;
    }
    __syncthreads();
}

__global__ void __launch_bounds__(NTHREADS, 1)
metasim_kernel(const float* __restrict__ Rg,
               const float* __restrict__ Tg,
               const float* __restrict__ rho0,
               float* __restrict__ out,
               int out_size)
{
    extern __shared__ char smem_raw[];
    __half* Rs_h = (__half*)smem_raw;                      // [ROWS][MM] fp16
    float*  part = (float*)(smem_raw + ROWS * MM * 2);     // [16 rows][2 halves]
    double* dsum = (double*)(part + 32);                   // [16], 8B aligned

    const int tid     = threadIdx.x;
    const int blk     = blockIdx.x;
    const int w       = tid >> 5;
    const int lane    = tid & 31;
    const int rowbase = blk * ROWS;
    const int row0    = 4 * (w >> 1);       // warp's 4-row group
    const int colhalf = w & 1;              // 0: cols 0..1023, 1: 1024..2047

    unsigned int gen = 0;
    if (tid == 0) {
        unsigned int c0;
        asm volatile("ld.relaxed.gpu.u32 %0, [%1];"
                     : "=r"(c0) : "l"(&g_bar_in) : "memory");
        gen = c0 / (unsigned)NBLK;          // exact multiple at launch boundary
    }

    // ---- convert this block's 16 fp32 R rows into fp16 SMEM (once) ----
    {
        const float4* Rg4 = (const float4*)Rg + (size_t)rowbase * (MM / 4);
        half2* Rs2 = (half2*)Rs_h;
        #pragma unroll 4
        for (int k = tid; k < ROWS * MM / 4; k += NTHREADS) {
            const float4 v = Rg4[k];
            Rs2[2 * k]     = __floats2half2_rn(v.x, v.y);
            Rs2[2 * k + 1] = __floats2half2_rn(v.z, v.w);
        }
    }

    // ---- per-row state lives in tid<16 (fp32 everywhere except R tile) ----
    const int myrow = rowbase + tid;        // valid for tid < ROWS
    float r0 = 0.f, r1 = 0.f, r2 = 0.f, r3 = 0.f, kk = 0.f;
    float Tr[16];
    if (tid < ROWS) {
        #pragma unroll
        for (int i = 0; i < 16; i++) Tr[i] = Tg[i];
        r0 = rho0[myrow * 4 + 0];
        r1 = rho0[myrow * 4 + 1];
        r2 = rho0[myrow * 4 + 2];
        r3 = rho0[myrow * 4 + 3];
        __stcg(&g_x[myrow], r0);            // initial x = rho0[:,0]
    }

    // ---- deterministic ntot from EXACT fp32 global R (column partials) ----
    for (int c = tid; c < MM; c += NTHREADS) {
        float s = 0.f;
        #pragma unroll
        for (int r = 0; r < ROWS; r++) s += Rg[(size_t)(rowbase + r) * MM + c];
        __stcg(&g_part[blk * MM + c], s);
    }

    gridsync(gen);                          // partials + g_x visible grid-wide

    if (tid < ROWS) {                       // ntot for own rows, fixed sum order
        float s = 0.f;
        #pragma unroll 8
        for (int bb = 0; bb < NBLK; bb++) s += __ldcg(&g_part[bb * MM + myrow]);
        kk = -BETA_F / s;
    }

    // warp's 4 fp16 R-row pointers (uint4 = 8 halves); c = colhalf*128+j*32+lane
    const uint4* R0 = (const uint4*)(Rs_h + (size_t)(row0 + 0) * MM);
    const uint4* R1 = (const uint4*)(Rs_h + (size_t)(row0 + 1) * MM);
    const uint4* R2 = (const uint4*)(Rs_h + (size_t)(row0 + 2) * MM);
    const uint4* R3 = (const uint4*)(Rs_h + (size_t)(row0 + 3) * MM);
    const int cbase = colhalf * 128 + lane; // this lane's private column slots

    double dAcc = 0.0;

    // dot helper macro: accumulate 8 cols (one uint4 of halves) into acc
    #define DOT8(acc, q, xvA, xvB) do {                                      \
        const half2* _h = (const half2*)&(q);                                \
        const float2 _f0 = __half22float2(_h[0]);                            \
        const float2 _f1 = __half22float2(_h[1]);                            \
        const float2 _f2 = __half22float2(_h[2]);                            \
        const float2 _f3 = __half22float2(_h[3]);                            \
        (acc) += _f0.x*(xvA).x + _f0.y*(xvA).y + _f1.x*(xvA).z + _f1.y*(xvA).w \
               + _f2.x*(xvB).x + _f2.y*(xvB).y + _f3.x*(xvB).z + _f3.y*(xvB).w; \
    } while (0)

    // one matvec phase: vec = g_x or g_p; results -> part[] (lane 0 of each warp)
    #define MATVEC_PHASE(VEC) do {                                           \
        const float4* _g4 = (const float4*)(VEC);                            \
        float4 _xA[4], _xB[4];                                               \
        _Pragma("unroll")                                                    \
        for (int j = 0; j < 4; j++) {      /* x straight into registers */   \
            const int c = cbase + j * 32;  /* per-lane-unique slots */       \
            _xA[j] = __ldcg(_g4 + 2 * c);                                    \
            _xB[j] = __ldcg(_g4 + 2 * c + 1);                                \
        }                                                                    \
        float _a0 = 0.f, _a1 = 0.f, _a2 = 0.f, _a3 = 0.f;                    \
        _Pragma("unroll")                                                    \
        for (int j = 0; j < 4; j++) {                                        \
            const int c = cbase + j * 32;                                    \
            const uint4 q0 = R0[c]; DOT8(_a0, q0, _xA[j], _xB[j]);           \
            const uint4 q1 = R1[c]; DOT8(_a1, q1, _xA[j], _xB[j]);           \
            const uint4 q2 = R2[c]; DOT8(_a2, q2, _xA[j], _xB[j]);           \
            const uint4 q3 = R3[c]; DOT8(_a3, q3, _xA[j], _xB[j]);           \
        }                                                                    \
        _Pragma("unroll")                                                    \
        for (int o = 16; o; o >>= 1) {                                       \
            _a0 += __shfl_xor_sync(0xffffffffu, _a0, o);                     \
            _a1 += __shfl_xor_sync(0xffffffffu, _a1, o);                     \
            _a2 += __shfl_xor_sync(0xffffffffu, _a2, o);                     \
            _a3 += __shfl_xor_sync(0xffffffffu, _a3, o);                     \
        }                                                                    \
        if (lane == 0) {                                                     \
            part[(row0 + 0) * 2 + colhalf] = _a0;                            \
            part[(row0 + 1) * 2 + colhalf] = _a1;                            \
            part[(row0 + 2) * 2 + colhalf] = _a2;                            \
            part[(row0 + 3) * 2 + colhalf] = _a3;                            \
        }                                                                    \
    } while (0)

    for (int t = 0; t < NSTEPS; t++) {
        // ===== Phase A: frac = R @ x ; p = 1 - exp(-beta*frac/ntot) =====
        MATVEC_PHASE(g_x);
        __syncthreads();
        if (tid < ROWS) {
            const float fr = part[2 * tid] + part[2 * tid + 1];
            __stcg(&g_p[myrow], 1.0f - expf(kk * fr));
        }
        gridsync(gen);

        // ===== Phase B: nw = R @ p ; compartment update ; traj out =====
        MATVEC_PHASE(g_p);
        __syncthreads();
        if (tid < ROWS) {
            const float acc = part[2 * tid] + part[2 * tid + 1];
            const float s   = r0 + r1 + r2 + r3;
            const float nw  = (1.0f - s) * acc;
            float n0 = r0 * Tr[0] + r1 * Tr[4] + r2 * Tr[8]  + r3 * Tr[12] + nw;
            float n1 = r0 * Tr[1] + r1 * Tr[5] + r2 * Tr[9]  + r3 * Tr[13];
            float n2 = r0 * Tr[2] + r1 * Tr[6] + r2 * Tr[10] + r3 * Tr[14];
            float n3 = r0 * Tr[3] + r1 * Tr[7] + r2 * Tr[11] + r3 * Tr[15];
            n0 = fminf(fmaxf(n0, 0.0f), 1e10f);
            n1 = fminf(fmaxf(n1, 0.0f), 1e10f);
            n2 = fminf(fmaxf(n2, 0.0f), 1e10f);
            n3 = fminf(fmaxf(n3, 0.0f), 1e10f);
            r0 = n0; r1 = n1; r2 = n2; r3 = n3;
            __stcg(&g_x[myrow], n0);                      // next step's x

            const float S = 1.0f - (n0 + n1 + n2 + n3);   // AddSusceptibleLayer
            float* o = out + ((size_t)t * MM + myrow) * (NC + 1);
            o[0] = S; o[1] = n0; o[2] = n1; o[3] = n2; o[4] = n3;
            dAcc += (double)(fabsf(S) + fabsf(n0) + fabsf(n1) + fabsf(n2) + fabsf(n3));
        }
        gridsync(gen);
    }
    #undef MATVEC_PHASE
    #undef DOT8

    // ---- agreement = mean(|traj|), fully deterministic reduction ----
    if (tid < ROWS) dsum[tid] = dAcc;
    __syncthreads();
    if (tid == 0) {
        double s = 0.0;
        for (int i = 0; i < ROWS; i++) s += dsum[i];
        __stcg(&g_bsum[blk], s);
    }
    gridsync(gen);
    if (blk == 0 && tid == 0 && out_size > TRAJ_ELEMS) {
        double s = 0.0;
        for (int i = 0; i < NBLK; i++) s += __ldcg(&g_bsum[i]);
        out[TRAJ_ELEMS] = (float)(s / (double)TRAJ_ELEMS);
    }
}

extern "C" void kernel_launch(void* const* d_in, const int* in_sizes, int n_in,
                              void* d_out, int out_size)
{
    // Identify inputs by element count: R: 2048*2048, T: 4*4, rho0: 2048*4
    const float* R    = nullptr;
    const float* Tm   = nullptr;
    const float* rho0 = nullptr;
    for (int i = 0; i < n_in; i++) {
        if      (in_sizes[i] == MM * MM) R    = (const float*)d_in[i];
        else if (in_sizes[i] == NC * NC) Tm   = (const float*)d_in[i];
        else if (in_sizes[i] == MM * NC) rho0 = (const float*)d_in[i];
    }
    if (!R    && n_in > 0) R    = (const float*)d_in[0];
    if (!Tm   && n_in > 1) Tm   = (const float*)d_in[1];
    if (!rho0 && n_in > 2) rho0 = (const float*)d_in[2];

    cudaFuncSetAttribute(metasim_kernel,
                         cudaFuncAttributeMaxDynamicSharedMemorySize,
                         SMEM_BYTES);

    metasim_kernel<<<NBLK, NTHREADS, SMEM_BYTES>>>(R, Tm, rho0,
                                                   (float*)d_out, out_size);
}